// round 4
// baseline (speedup 1.0000x reference)
#include <cuda_runtime.h>
#include <math.h>

#define NMODES      6400
#define NB          25            // blocks of 256 over modes
#define NBINS       260           // lifetime bins (0..258)
#define CHUNK       512           // samples per warp-chunk = 32 lanes * U
#define U           16            // accumulators per lane
#define G           64            // mode groups (partial buffers)
#define MAX_SAMPLES 132096
#define MAX_CHUNKS  258
#define TLN         18.0f         // -ln(~1.5e-8) relative amplitude cutoff

// Static scratch (no runtime allocation allowed)
__device__ float4       g_uA[NMODES], g_uB[NMODES];   // unsorted per-mode params
__device__ int          g_Lm[NMODES];                 // lifetime in chunks
__device__ int          g_hist2[NBINS][NB];
__device__ int          g_cnt[MAX_CHUNKS];            // #active modes at chunk c
__device__ float4       g_pA[NMODES], g_pB[NMODES];   // lifetime-sorted params
__device__ float        g_partial[(size_t)G * MAX_SAMPLES];
__device__ unsigned int g_maxbits;
__device__ unsigned int g_done;

__device__ __forceinline__ float softplusf(float x) {
    return (x > 20.f) ? x : log1pf(expf(x));
}

// 2pi split for Cody-Waite (compile-time constants)
#define INV2PI 0.15915494309189535f
#define P2_0   6.28125f
#define P2_1   ((float)(6.283185307179586476925 - 6.28125))
#define P2_2   ((float)(6.283185307179586476925 - 6.28125 \
                        - (double)(float)(6.283185307179586476925 - 6.28125)))

// ---------------------------------------------------------------------------
// P1: per-mode params, lifetime, per-block lifetime histogram. 25 x 256.
// ---------------------------------------------------------------------------
__global__ void p1_kernel(const float* mu_raw, const float* D_raw,
                          const float* T0_raw, const float* Ly_raw,
                          const float* xo_raw, const float* yo_raw,
                          int nchunks)
{
    __shared__ int sh_hist[NBINS];
    int tid = threadIdx.x, b = blockIdx.x;
    for (int i = tid; i < NBINS; i += 256) sh_hist[i] = 0;
    if (b == 0 && tid == 0) { g_maxbits = 0u; g_done = 0u; }
    __syncthreads();

    int m = b * 256 + tid;

    const float PI    = 3.14159265358979323846f;
    const float LX    = 0.5f;
    const float Kf    = 1.0f / 44100.0f;
    const float MAXOM = (float)(20000.0 * M_PI);
    const float MINOM = (float)(40.0 * M_PI);
    const float ALPHA = (float)(3.0 * 2.302585092994045684 / 6.0);
    const float BETA  = (float)(3.0 * 2.302585092994045684
                                / ((2.0 * M_PI * 500.0) * (2.0 * M_PI * 500.0))
                                * (1.0 - 1.0 / 6.0));

    float mu = softplusf(mu_raw[0]) + 1e-4f;
    float Dm = softplusf(D_raw[0])  + 1e-4f;
    float T0 = softplusf(T0_raw[0]) + 1e-4f;
    float Ly = 1.1f + (4.0f - 1.1f) * ((tanhf(Ly_raw[0]) + 1.0f) * 0.5f);
    float xo = 0.49f * LX + (1.0f - 0.49f) * LX * ((tanhf(xo_raw[0]) + 1.0f) * 0.5f);
    float yo = 0.51f * Ly + (1.0f - 0.51f) * Ly * ((tanhf(yo_raw[0]) + 1.0f) * 0.5f);
    float xi = 0.1f * LX;
    float yi = 0.1f * Ly;

    float Mf = (float)(m / 80 + 1);
    float Nf = (float)(m % 80 + 1);

    float a1 = Mf * PI / LX;
    float a2 = Nf * PI / Ly;
    float g1 = a1 * a1 + a2 * a2;
    float om2 = T0 * g1 + Dm * g1 * g1;
    float omega = sqrtf(fmaxf(om2, 0.f));
    bool valid = (omega <= MAXOM) && (omega >= MINOM);

    float in_w  = cosf(xi * PI * Mf / LX) * cosf(yi * PI * Nf / Ly);
    float out_w = cosf(xo * PI * Mf / LX) * cosf(yo * PI * Nf / Ly);
    float sigma = ALPHA + BETA * omega * omega;
    float msf   = 0.25f * mu * LX * Ly;
    float theta = omega * Kf;
    float denom = sinf(theta) + 1e-8f;
    float sigK  = sigma * Kf;

    // s[n] = C * r^n * sin(n*theta), r = exp(-sigma*K)
    float Cf = out_w * in_w * (Kf * Kf) / (msf * denom);

    int L = 0;
    float c1f = 0.f, c2f = 0.f, rinv32f = 0.f, cs32f = 0.f, sn32f = 0.f;
    if (valid) {
        // 32*theta is an exact fp32 product (exponent shift)
        float x  = 32.f * theta;
        float k  = rintf(x * INV2PI);
        float rr = fmaf(-k, P2_0, x);
        rr = fmaf(-k, P2_1, rr);
        rr = fmaf(-k, P2_2, rr);
        float c32 = cosf(rr);
        float s32 = sinf(rr);
        float r32 = expf(-32.f * sigK);
        c1f     = 2.f * r32 * c32;
        c2f     = r32 * r32;
        rinv32f = 1.f / r32;
        cs32f   = c32;
        sn32f   = s32;
        float lc = TLN / (sigK * (float)CHUNK);
        int   Li = (lc >= (float)nchunks) ? nchunks : ((int)lc + 1);
        L = (Li > nchunks) ? nchunks : Li;
        if (L < 1) L = 1;
    }

    g_uA[m] = make_float4(theta, -sigK, c1f, c2f);
    g_uB[m] = make_float4(rinv32f, cs32f, sn32f, valid ? Cf : 0.f);
    g_Lm[m] = L;
    atomicAdd(&sh_hist[L], 1);
    __syncthreads();
    for (int i = tid; i < NBINS; i += 256) g_hist2[i][b] = sh_hist[i];
}

// ---------------------------------------------------------------------------
// P3: every block recomputes bin offsets from the (lifetime, block)
// histogram, then scatters its 256 modes deterministically.
// Sort: descending lifetime, ascending block, original order within block.
// ---------------------------------------------------------------------------
__global__ void p3_kernel(int nchunks)
{
    __shared__ int offL[NBINS];   // global start of each lifetime bin
    __shared__ int preB[NBINS];   // within-bin offset contributed by blocks < b
    __shared__ int shL[256];
    int tid = threadIdx.x, b = blockIdx.x;

    for (int i = tid; i < NBINS; i += 256) {
        int tot = 0, pre = 0;
#pragma unroll
        for (int bb = 0; bb < NB; bb++) {
            int h = g_hist2[i][bb];
            tot += h;
            if (bb < b) pre += h;
        }
        offL[i] = tot;            // totals for now
        preB[i] = pre;
    }
    __syncthreads();
    if (tid == 0) {
        int run = 0;
        for (int L = NBINS - 1; L >= 0; --L) { int h = offL[L]; offL[L] = run; run += h; }
    }
    __syncthreads();
    if (b == 0)
        for (int c = tid; c < nchunks; c += 256) g_cnt[c] = offL[c];

    int m = b * 256 + tid;
    int L = g_Lm[m];
    shL[tid] = L;
    __syncthreads();
    int local = 0;
    for (int i = 0; i < tid; i++) local += (shL[i] == L);
    int rank = offL[L] + preB[L] + local;
    g_pA[rank] = g_uA[m];
    g_pB[rank] = g_uB[m];
}

// ---------------------------------------------------------------------------
// Modal synthesis. One warp = (chunk c, group g), w = c*G + g so blocks have
// uniform work and heavy chunks launch first. Lane l carries samples
// n0+l+32j via TWO independent stride-64 recurrences (even/odd j).
// Seeds (the R3 bug, now fixed):
//   even chain: cur0 = s[n],    prev0 = s[n-64]
//   odd  chain: cur1 = s[n+32], prev1 = s[n-32]
// ---------------------------------------------------------------------------
__global__ void __launch_bounds__(256) modal_kernel(int N, int nchunks)
{
    int w    = (int)((blockIdx.x * blockDim.x + threadIdx.x) >> 5);
    int lane = threadIdx.x & 31;
    int total = nchunks * G;
    if (w >= total) return;
    int c = w / G;
    int g = w % G;
    int n0 = c * CHUNK;

    int cnt  = g_cnt[c];
    int base = (cnt * g) >> 6;          // G == 64
    int end  = (cnt * (g + 1)) >> 6;

    float acc[U];
#pragma unroll
    for (int j = 0; j < U; j++) acc[j] = 0.f;

    float lf  = (float)lane;
    float n0f = (float)n0;

    for (int r = base; r < end; ++r) {
        float4 pa = g_pA[r];
        float4 pb = g_pB[r];
        float theta = pa.x, msigK = pa.y, c1 = pa.z, c2 = pa.w;
        float rinv32 = pb.x, cs32 = pb.y, sn32 = pb.z, C = pb.w;

        // chunk phase: (n0 * theta) mod 2pi, exact product + 3-term reduction
        float p  = n0f * theta;
        float e  = fmaf(n0f, theta, -p);
        float k  = rintf(p * INV2PI);
        float rr = fmaf(-k, P2_0, p);
        rr = fmaf(-k, P2_1, rr);
        rr = fmaf(-k, P2_2, rr);
        float psi = rr + e;

        // per-lane phase and amplitude
        float a  = fmaf(lf, theta, psi);
        float k2 = rintf(a * INV2PI);
        a = fmaf(-k2, P2_0, a);
        a = fmaf(-k2, P2_1, a);
        float s, co;
        __sincosf(a, &s, &co);
        float Ae = C * __expf(msigK * (n0f + lf));

        // rotation terms for -32 and -64 steps
        float cs64   = fmaf(2.f * cs32, cs32, -1.f);   // cos(64*theta)
        float sn64   = 2.f * sn32 * cs32;              // sin(64*theta)
        float rinv64 = rinv32 * rinv32;

        float cur0  = Ae * s;                                      // s[n]
        float prev1 = (Ae * rinv32) * fmaf(s, cs32, -co * sn32);   // s[n-32]
        float prev0 = (Ae * rinv64) * fmaf(s, cs64, -co * sn64);   // s[n-64]
        float cur1  = fmaf(c1, cur0, -(c2 * prev1));               // s[n+32]

        // stride-64 coefficients: 2 r^64 cos(64th) = c1^2 - 2 c2 ; r^128 = c2^2
        float c1q = fmaf(c1, c1, -(c2 + c2));
        float c2q = c2 * c2;

#pragma unroll
        for (int jj = 0; jj < U / 2; jj++) {
            acc[2 * jj]     += cur0;
            acc[2 * jj + 1] += cur1;
            float n0x = fmaf(c1q, cur0, -(c2q * prev0));
            float n1x = fmaf(c1q, cur1, -(c2q * prev1));
            prev0 = cur0; cur0 = n0x;
            prev1 = cur1; cur1 = n1x;
        }
    }

    float* dst = g_partial + (size_t)g * MAX_SAMPLES + n0 + lane;
#pragma unroll
    for (int j = 0; j < U; j++) {
        int n = n0 + 32 * j + lane;
        if (n < N) dst[32 * j] = acc[j];
    }
}

// ---------------------------------------------------------------------------
// Fused reduce + normalize (threadfence last-block pattern; peak via
// atomicMax on float bits is order-independent -> deterministic output).
// ---------------------------------------------------------------------------
__global__ void reduce_norm_kernel(float* out, int N)
{
    int n = blockIdx.x * blockDim.x + threadIdx.x;
    float v = 0.f;
    if (n < N) {
#pragma unroll
        for (int g = 0; g < G; g++)
            v += g_partial[(size_t)g * MAX_SAMPLES + n];
        out[n] = v;
    }
    float am = (n < N) ? fabsf(v) : 0.f;
#pragma unroll
    for (int o = 16; o; o >>= 1)
        am = fmaxf(am, __shfl_xor_sync(0xffffffffu, am, o));
    __shared__ float wmax[8];
    __shared__ unsigned int ticket;
    int wr = threadIdx.x >> 5;
    if ((threadIdx.x & 31) == 0) wmax[wr] = am;
    __syncthreads();
    if (threadIdx.x == 0) {
        float bm = wmax[0];
        int nw = (blockDim.x + 31) >> 5;
        for (int i = 1; i < nw; i++) bm = fmaxf(bm, wmax[i]);
        atomicMax(&g_maxbits, __float_as_uint(bm));
        __threadfence();
        ticket = atomicAdd(&g_done, 1u);
    }
    __syncthreads();
    if (ticket == gridDim.x - 1) {
        __threadfence();
        unsigned int pk = atomicMax(&g_maxbits, 0u);   // atomic read (L2)
        float inv = 1.f / (__uint_as_float(pk) + 1e-8f);
        for (int i = threadIdx.x; i < N; i += blockDim.x)
            out[i] = __ldcg(out + i) * inv;            // bypass L1: see peers' data
    }
}

// ---------------------------------------------------------------------------
extern "C" void kernel_launch(void* const* d_in, const int* in_sizes, int n_in,
                              void* d_out, int out_size)
{
    const float* mu_raw = (const float*)d_in[0];
    const float* D_raw  = (const float*)d_in[1];
    const float* T0_raw = (const float*)d_in[2];
    const float* Ly_raw = (const float*)d_in[3];
    const float* xo_raw = (const float*)d_in[4];
    const float* yo_raw = (const float*)d_in[5];

    int N = out_size;
    if (N > MAX_SAMPLES) N = MAX_SAMPLES;
    int nchunks = (N + CHUNK - 1) / CHUNK;

    p1_kernel<<<NB, 256>>>(mu_raw, D_raw, T0_raw, Ly_raw, xo_raw, yo_raw, nchunks);
    p3_kernel<<<NB, 256>>>(nchunks);

    int total_warps = nchunks * G;
    int blocks = (total_warps * 32 + 255) / 256;
    modal_kernel<<<blocks, 256>>>(N, nchunks);

    int rb = (N + 255) / 256;
    reduce_norm_kernel<<<rb, 256>>>((float*)d_out, N);
}

// round 5
// speedup vs baseline: 1.9828x; 1.9828x over previous
#include <cuda_runtime.h>
#include <math.h>

#define NMODES      6400
#define NB          25            // blocks of 256 over modes
#define NBINS       260           // lifetime bins (0..258)
#define CHUNK       512           // samples per warp-chunk = 32 lanes * U
#define U           16            // accumulators per lane
#define G           64            // mode groups (partial buffers)
#define MAX_SAMPLES 132096
#define MAX_CHUNKS  258
#define TLN         18.0f         // -ln(~1.5e-8) relative amplitude cutoff

// Static scratch (no runtime allocation allowed)
__device__ float4       g_uA[NMODES], g_uB[NMODES];   // unsorted per-mode params
__device__ int          g_Lm[NMODES];                 // lifetime in chunks
__device__ int          g_hist2[NBINS][NB];
__device__ int          g_cnt[MAX_CHUNKS];            // #active modes at chunk c
__device__ float4       g_pA[NMODES], g_pB[NMODES];   // lifetime-sorted params
__device__ float        g_partial[(size_t)G * MAX_SAMPLES];
__device__ unsigned int g_maxbits;

__device__ __forceinline__ float softplusf(float x) {
    return (x > 20.f) ? x : log1pf(expf(x));
}

// 2pi split for Cody-Waite (compile-time constants)
#define INV2PI 0.15915494309189535f
#define P2_0   6.28125f
#define P2_1   ((float)(6.283185307179586476925 - 6.28125))
#define P2_2   ((float)(6.283185307179586476925 - 6.28125 \
                        - (double)(float)(6.283185307179586476925 - 6.28125)))

// ---------------------------------------------------------------------------
// P1: per-mode params, lifetime, per-block lifetime histogram. 25 x 256.
// ---------------------------------------------------------------------------
__global__ void p1_kernel(const float* mu_raw, const float* D_raw,
                          const float* T0_raw, const float* Ly_raw,
                          const float* xo_raw, const float* yo_raw,
                          int nchunks)
{
    __shared__ int sh_hist[NBINS];
    int tid = threadIdx.x, b = blockIdx.x;
    for (int i = tid; i < NBINS; i += 256) sh_hist[i] = 0;
    if (b == 0 && tid == 0) g_maxbits = 0u;
    __syncthreads();

    int m = b * 256 + tid;

    const float PI    = 3.14159265358979323846f;
    const float LX    = 0.5f;
    const float Kf    = 1.0f / 44100.0f;
    const float MAXOM = (float)(20000.0 * M_PI);
    const float MINOM = (float)(40.0 * M_PI);
    const float ALPHA = (float)(3.0 * 2.302585092994045684 / 6.0);
    const float BETA  = (float)(3.0 * 2.302585092994045684
                                / ((2.0 * M_PI * 500.0) * (2.0 * M_PI * 500.0))
                                * (1.0 - 1.0 / 6.0));

    float mu = softplusf(mu_raw[0]) + 1e-4f;
    float Dm = softplusf(D_raw[0])  + 1e-4f;
    float T0 = softplusf(T0_raw[0]) + 1e-4f;
    float Ly = 1.1f + (4.0f - 1.1f) * ((tanhf(Ly_raw[0]) + 1.0f) * 0.5f);
    float xo = 0.49f * LX + (1.0f - 0.49f) * LX * ((tanhf(xo_raw[0]) + 1.0f) * 0.5f);
    float yo = 0.51f * Ly + (1.0f - 0.51f) * Ly * ((tanhf(yo_raw[0]) + 1.0f) * 0.5f);
    float xi = 0.1f * LX;
    float yi = 0.1f * Ly;

    float Mf = (float)(m / 80 + 1);
    float Nf = (float)(m % 80 + 1);

    float a1 = Mf * PI / LX;
    float a2 = Nf * PI / Ly;
    float g1 = a1 * a1 + a2 * a2;
    float om2 = T0 * g1 + Dm * g1 * g1;
    float omega = sqrtf(fmaxf(om2, 0.f));
    bool valid = (omega <= MAXOM) && (omega >= MINOM);

    float in_w  = cosf(xi * PI * Mf / LX) * cosf(yi * PI * Nf / Ly);
    float out_w = cosf(xo * PI * Mf / LX) * cosf(yo * PI * Nf / Ly);
    float sigma = ALPHA + BETA * omega * omega;
    float msf   = 0.25f * mu * LX * Ly;
    float theta = omega * Kf;
    float denom = sinf(theta) + 1e-8f;
    float sigK  = sigma * Kf;

    // s[n] = C * r^n * sin(n*theta), r = exp(-sigma*K)
    float Cf = out_w * in_w * (Kf * Kf) / (msf * denom);

    int L = 0;
    float c1f = 0.f, c2f = 0.f, rinv32f = 0.f, cs32f = 0.f, sn32f = 0.f;
    if (valid) {
        // 32*theta is an exact fp32 product (exponent shift)
        float x  = 32.f * theta;
        float k  = rintf(x * INV2PI);
        float rr = fmaf(-k, P2_0, x);
        rr = fmaf(-k, P2_1, rr);
        rr = fmaf(-k, P2_2, rr);
        float c32 = cosf(rr);
        float s32 = sinf(rr);
        float r32 = expf(-32.f * sigK);
        c1f     = 2.f * r32 * c32;
        c2f     = r32 * r32;
        rinv32f = 1.f / r32;
        cs32f   = c32;
        sn32f   = s32;
        float lc = TLN / (sigK * (float)CHUNK);
        int   Li = (lc >= (float)nchunks) ? nchunks : ((int)lc + 1);
        L = (Li > nchunks) ? nchunks : Li;
        if (L < 1) L = 1;
    }

    g_uA[m] = make_float4(theta, -sigK, c1f, c2f);
    g_uB[m] = make_float4(rinv32f, cs32f, sn32f, valid ? Cf : 0.f);
    g_Lm[m] = L;
    atomicAdd(&sh_hist[L], 1);
    __syncthreads();
    for (int i = tid; i < NBINS; i += 256) g_hist2[i][b] = sh_hist[i];
}

// ---------------------------------------------------------------------------
// P3: every block recomputes bin offsets from the (lifetime, block)
// histogram, then scatters its 256 modes deterministically.
// Sort: descending lifetime, ascending block, original order within block.
// ---------------------------------------------------------------------------
__global__ void p3_kernel(int nchunks)
{
    __shared__ int offL[NBINS];   // global start of each lifetime bin
    __shared__ int preB[NBINS];   // within-bin offset contributed by blocks < b
    __shared__ int shL[256];
    int tid = threadIdx.x, b = blockIdx.x;

    for (int i = tid; i < NBINS; i += 256) {
        int tot = 0, pre = 0;
#pragma unroll
        for (int bb = 0; bb < NB; bb++) {
            int h = g_hist2[i][bb];
            tot += h;
            if (bb < b) pre += h;
        }
        offL[i] = tot;            // totals for now
        preB[i] = pre;
    }
    __syncthreads();
    if (tid == 0) {
        int run = 0;
        for (int L = NBINS - 1; L >= 0; --L) { int h = offL[L]; offL[L] = run; run += h; }
    }
    __syncthreads();
    if (b == 0)
        for (int c = tid; c < nchunks; c += 256) g_cnt[c] = offL[c];

    int m = b * 256 + tid;
    int L = g_Lm[m];
    shL[tid] = L;
    __syncthreads();
    int local = 0;
    for (int i = 0; i < tid; i++) local += (shL[i] == L);
    int rank = offL[L] + preB[L] + local;
    g_pA[rank] = g_uA[m];
    g_pB[rank] = g_uB[m];
}

// ---------------------------------------------------------------------------
// Modal synthesis. One warp = (chunk c, group g), w = c*G + g so blocks have
// uniform work and heavy chunks launch first. Lane l carries samples
// n0+l+32j via TWO independent stride-64 recurrences (even/odd j).
// Seeds: even chain cur0=s[n], prev0=s[n-64]; odd chain cur1=s[n+32],
// prev1=s[n-32]. Exact init via float Dekker + Cody-Waite.
// ---------------------------------------------------------------------------
__global__ void __launch_bounds__(256) modal_kernel(int N, int nchunks)
{
    int w    = (int)((blockIdx.x * blockDim.x + threadIdx.x) >> 5);
    int lane = threadIdx.x & 31;
    int total = nchunks * G;
    if (w >= total) return;
    int c = w / G;
    int g = w % G;
    int n0 = c * CHUNK;

    int cnt  = g_cnt[c];
    int base = (cnt * g) >> 6;          // G == 64
    int end  = (cnt * (g + 1)) >> 6;

    float acc[U];
#pragma unroll
    for (int j = 0; j < U; j++) acc[j] = 0.f;

    float lf  = (float)lane;
    float n0f = (float)n0;

    for (int r = base; r < end; ++r) {
        float4 pa = g_pA[r];
        float4 pb = g_pB[r];
        float theta = pa.x, msigK = pa.y, c1 = pa.z, c2 = pa.w;
        float rinv32 = pb.x, cs32 = pb.y, sn32 = pb.z, C = pb.w;

        // chunk phase: (n0 * theta) mod 2pi, exact product + 3-term reduction
        float p  = n0f * theta;
        float e  = fmaf(n0f, theta, -p);
        float k  = rintf(p * INV2PI);
        float rr = fmaf(-k, P2_0, p);
        rr = fmaf(-k, P2_1, rr);
        rr = fmaf(-k, P2_2, rr);
        float psi = rr + e;

        // per-lane phase and amplitude
        float a  = fmaf(lf, theta, psi);
        float k2 = rintf(a * INV2PI);
        a = fmaf(-k2, P2_0, a);
        a = fmaf(-k2, P2_1, a);
        float s, co;
        __sincosf(a, &s, &co);
        float Ae = C * __expf(msigK * (n0f + lf));

        // rotation terms for -32 and -64 steps
        float cs64   = fmaf(2.f * cs32, cs32, -1.f);   // cos(64*theta)
        float sn64   = 2.f * sn32 * cs32;              // sin(64*theta)
        float rinv64 = rinv32 * rinv32;

        float cur0  = Ae * s;                                      // s[n]
        float prev1 = (Ae * rinv32) * fmaf(s, cs32, -co * sn32);   // s[n-32]
        float prev0 = (Ae * rinv64) * fmaf(s, cs64, -co * sn64);   // s[n-64]
        float cur1  = fmaf(c1, cur0, -(c2 * prev1));               // s[n+32]

        // stride-64 coefficients: 2 r^64 cos(64th) = c1^2 - 2 c2 ; r^128 = c2^2
        float c1q = fmaf(c1, c1, -(c2 + c2));
        float c2q = c2 * c2;

#pragma unroll
        for (int jj = 0; jj < U / 2; jj++) {
            acc[2 * jj]     += cur0;
            acc[2 * jj + 1] += cur1;
            float n0x = fmaf(c1q, cur0, -(c2q * prev0));
            float n1x = fmaf(c1q, cur1, -(c2q * prev1));
            prev0 = cur0; cur0 = n0x;
            prev1 = cur1; cur1 = n1x;
        }
    }

    float* dst = g_partial + (size_t)g * MAX_SAMPLES + n0 + lane;
#pragma unroll
    for (int j = 0; j < U; j++) {
        int n = n0 + 32 * j + lane;
        if (n < N) dst[32 * j] = acc[j];
    }
}

// ---------------------------------------------------------------------------
// Sum the G partial buffers, write unnormalized output, track peak.
// ---------------------------------------------------------------------------
__global__ void reduce_kernel(float* out, int N)
{
    int n = blockIdx.x * blockDim.x + threadIdx.x;
    float v = 0.f;
    if (n < N) {
#pragma unroll
        for (int g = 0; g < G; g++)
            v += g_partial[(size_t)g * MAX_SAMPLES + n];
        out[n] = v;
    }
    float am = (n < N) ? fabsf(v) : 0.f;
#pragma unroll
    for (int o = 16; o; o >>= 1)
        am = fmaxf(am, __shfl_xor_sync(0xffffffffu, am, o));
    __shared__ float wmax[8];
    int wr = threadIdx.x >> 5;
    if ((threadIdx.x & 31) == 0) wmax[wr] = am;
    __syncthreads();
    if (threadIdx.x == 0) {
        float bm = wmax[0];
        int nw = (blockDim.x + 31) >> 5;
        for (int i = 1; i < nw; i++) bm = fmaxf(bm, wmax[i]);
        atomicMax(&g_maxbits, __float_as_uint(bm));   // abs vals >= 0: int-monotonic
    }
}

__global__ void norm_kernel(float* out, int N)
{
    int n = blockIdx.x * blockDim.x + threadIdx.x;
    if (n < N) {
        float inv = 1.0f / (__uint_as_float(g_maxbits) + 1e-8f);
        out[n] = out[n] * inv;
    }
}

// ---------------------------------------------------------------------------
extern "C" void kernel_launch(void* const* d_in, const int* in_sizes, int n_in,
                              void* d_out, int out_size)
{
    const float* mu_raw = (const float*)d_in[0];
    const float* D_raw  = (const float*)d_in[1];
    const float* T0_raw = (const float*)d_in[2];
    const float* Ly_raw = (const float*)d_in[3];
    const float* xo_raw = (const float*)d_in[4];
    const float* yo_raw = (const float*)d_in[5];

    int N = out_size;
    if (N > MAX_SAMPLES) N = MAX_SAMPLES;
    int nchunks = (N + CHUNK - 1) / CHUNK;

    p1_kernel<<<NB, 256>>>(mu_raw, D_raw, T0_raw, Ly_raw, xo_raw, yo_raw, nchunks);
    p3_kernel<<<NB, 256>>>(nchunks);

    int total_warps = nchunks * G;
    int blocks = (total_warps * 32 + 255) / 256;
    modal_kernel<<<blocks, 256>>>(N, nchunks);

    int rb = (N + 255) / 256;
    reduce_kernel<<<rb, 256>>>((float*)d_out, N);
    norm_kernel<<<rb, 256>>>((float*)d_out, N);
}